// round 12
// baseline (speedup 1.0000x reference)
#include <cuda_runtime.h>
#include <cuda_bf16.h>
#include <stdint.h>

#define N_POINTS  1048576
#define DD        64
#define NUM_BINS  (DD*DD*DD)         // 262144
#define LL        128
#define TT        8
#define CAP       8
#define STORE_CAP 32

#define LAT_ELEMS  (LL*LL*LL*TT)     // 16777216
#define BUF_ELEMS  (NUM_BINS*CAP*3)
#define PLANE      (LL*LL*LL)        // 2097152 floats per type-plane
#define XSLICE     (LL*LL)           // 16384

// grids
#define BIN_BLOCKS   (N_POINTS/4/256)             // 1024 (4 points/thread)
#define ZERO_BLOCKS  (BIN_BLOCKS*4)               // 4096 (4 float4 stores/thread)
#define A_BLOCKS     (BIN_BLOCKS*5)               // 5120, groups of 5 (1 bin + 4 zero)
#define ZERO_STRIDE  (ZERO_BLOCKS*256)            // 1048576 float4s between stores
#define SPLAT_BLOCKS (NUM_BINS*4/256)             // 4096 (4 slots/bin)
#define TR_BLOCKS    (PLANE/256)                  // 8192
#define FILL_BLOCKS  (NUM_BINS/256)               // 1024
#define C_BLOCKS     (FILL_BLOCKS*9)              // 9216, groups of 9 (8 tr + 1 fill)

__device__ int    g_count[NUM_BINS];
__device__ __align__(16)  float4 g_pts[NUM_BINS * STORE_CAP]; // (x,y,z,(idx<<3)|t)
__device__ __align__(128) float  g_scr[TT * PLANE];           // [t][x][y][z]

// ---- vector reduction ------------------------------------------------------
__device__ __forceinline__ void red4(float* p, float a, float b, float c, float d) {
    asm volatile("red.global.add.v4.f32 [%0], {%1,%2,%3,%4};"
                 :: "l"(p), "f"(a), "f"(b), "f"(c), "f"(d) : "memory");
}

// ---- scalar bounds-checked splat (boundary + overflow path) ----------------
__device__ __forceinline__ void splat_scalar(float px, float py, float pz, int t)
{
    int cx = (int)floorf(px * 4.0f);
    int cy = (int)floorf(py * 4.0f);
    int cz = (int)floorf(pz * 4.0f);

    const float inv = 1.0f / (2.0f * 0.3f * 0.3f);
    float ex[3], ey[3], ez[3];
    #pragma unroll
    for (int o = 0; o < 3; o++) {
        float vx = px - ((float)(cx + o - 1) + 0.5f) * 0.25f;
        float vy = py - ((float)(cy + o - 1) + 0.5f) * 0.25f;
        float vz = pz - ((float)(cz + o - 1) + 0.5f) * 0.25f;
        ex[o] = __expf(-vx * vx * inv);
        ey[o] = __expf(-vy * vy * inv);
        ez[o] = __expf(-vz * vz * inv);
    }
    float* pl = g_scr + (size_t)t * PLANE;
    #pragma unroll
    for (int ix = 0; ix < 3; ix++) {
        int x = cx + ix - 1;
        if ((unsigned)x >= (unsigned)LL) continue;
        #pragma unroll
        for (int iy = 0; iy < 3; iy++) {
            int y = cy + iy - 1;
            if ((unsigned)y >= (unsigned)LL) continue;
            float exy = ex[ix] * ey[iy];
            #pragma unroll
            for (int iz = 0; iz < 3; iz++) {
                int z = cz + iz - 1;
                if ((unsigned)z >= (unsigned)LL) continue;
                atomicAdd(pl + x * XSLICE + y * LL + z, exy * ez[iz]);
            }
        }
    }
}

// ---- bin one point ----------------------------------------------------------
__device__ __forceinline__ void bin_point(float px, float py, float pz,
                                          int mk, int t, int i)
{
    if (!mk) return;
    int bx = min(max((int)floorf(px * 2.0f), 0), DD - 1);
    int by = min(max((int)floorf(py * 2.0f), 0), DD - 1);
    int bz = min(max((int)floorf(pz * 2.0f), 0), DD - 1);
    int bin = (bx * DD + by) * DD + bz;
    int pos = atomicAdd(&g_count[bin], 1);
    if (pos < STORE_CAP) {
        g_pts[bin * STORE_CAP + pos] =
            make_float4(px, py, pz, __int_as_float((i << 3) | t));
    } else {
        splat_scalar(px, py, pz, t);   // P ~ 1e-22, keeps result exact
    }
}

// ---------------------------------------------------------------------------
// Kernel A: interleaved [zero g_scr | bin scatter], groups of 5.
// Zero blocks: 4 grid-strided float4 stores/thread (L2 prefetch of scratch).
// Bin blocks: 4 points/thread with vectorized loads.
// ---------------------------------------------------------------------------
__global__ void __launch_bounds__(256)
zero_bin_kernel(const float* __restrict__ pts,
                const int* __restrict__ mask,
                const int* __restrict__ types)
{
    int g = blockIdx.x;
    int k = g / 5;
    int r = g - k * 5;

    if (r != 0) {
        int zid = (k * 4 + (r - 1)) * 256 + threadIdx.x;
        float4* s = (float4*)g_scr;
        #pragma unroll
        for (int j = 0; j < 4; j++)
            s[zid + j * ZERO_STRIDE] = make_float4(0.f, 0.f, 0.f, 0.f);
        return;
    }

    int q = k * 256 + threadIdx.x;       // quad index [0, N/4)
    int base = q * 4;

    const float4* p4 = (const float4*)(pts + 3 * (size_t)base);
    float4 a = p4[0];
    float4 b = p4[1];
    float4 c = p4[2];
    int4 mk = ((const int4*)mask)[q];
    int4 ty = ((const int4*)types)[q];

    bin_point(a.x, a.y, a.z, mk.x, ty.x, base + 0);
    bin_point(a.w, b.x, b.y, mk.y, ty.y, base + 1);
    bin_point(b.z, b.w, c.x, mk.z, ty.z, base + 2);
    bin_point(c.y, c.z, c.w, mk.w, ty.w, base + 3);
}

// ---------------------------------------------------------------------------
// Kernel B: splat only (bin = tid/4, slot = tid%4) — shifted-u8 two-red4.
// ---------------------------------------------------------------------------
__global__ void __launch_bounds__(256)
splat_kernel()
{
    int tid = blockIdx.x * 256 + threadIdx.x;
    int bin  = tid >> 2;
    int slot = tid & 3;

    int m = min(g_count[bin], STORE_CAP);
    for (int s = slot; s < m; s += 4) {
        float4 r = g_pts[bin * STORE_CAP + s];
        float px = r.x, py = r.y, pz = r.z;
        int t = __float_as_int(r.w) & 7;

        int cx = (int)floorf(px * 4.0f);
        int cy = (int)floorf(py * 4.0f);
        int cz = (int)floorf(pz * 4.0f);

        bool interior = ((unsigned)(cx - 1) < (unsigned)(LL - 2)) &&
                        ((unsigned)(cy - 1) < (unsigned)(LL - 2)) &&
                        ((unsigned)(cz - 1) < (unsigned)(LL - 2));
        if (!interior) { splat_scalar(px, py, pz, t); continue; }

        const float inv = 1.0f / (2.0f * 0.3f * 0.3f);
        float ex[3], ey[3], ez[3];
        #pragma unroll
        for (int o = 0; o < 3; o++) {
            float vx = px - ((float)(cx + o - 1) + 0.5f) * 0.25f;
            float vy = py - ((float)(cy + o - 1) + 0.5f) * 0.25f;
            float vz = pz - ((float)(cz + o - 1) + 0.5f) * 0.25f;
            ex[o] = __expf(-vx * vx * inv);
            ey[o] = __expf(-vy * vy * inv);
            ez[o] = __expf(-vz * vz * inv);
        }

        int zb = cz - 1;
        int a  = zb & 3;

        float u[8];
        #pragma unroll
        for (int q = 0; q < 8; q++) {
            int d = q - a;
            u[q] = (d == 0) ? ez[0] : (d == 1) ? ez[1] : (d == 2) ? ez[2] : 0.0f;
        }
        bool two = (a >= 2);

        float* q0 = g_scr + (size_t)t * PLANE
                  + (cx - 1) * XSLICE + (cy - 1) * LL + (zb - a);

        #pragma unroll
        for (int ix = 0; ix < 3; ix++) {
            #pragma unroll
            for (int iy = 0; iy < 3; iy++) {
                float w = ex[ix] * ey[iy];
                float* p = q0 + ix * XSLICE + iy * LL;
                red4(p, w*u[0], w*u[1], w*u[2], w*u[3]);
                if (two)
                    red4(p + 4, w*u[4], w*u[5], w*u[6], w*u[7]);
            }
        }
    }
}

// ---------------------------------------------------------------------------
// transpose work for one block: [t][x][y][z] -> [x][y][z][t]
// ---------------------------------------------------------------------------
__device__ __forceinline__ void do_transpose(int tb, float* __restrict__ lat)
{
    int v = tb * 256 + threadIdx.x;   // (x*128+y)*128+z

    float o[TT];
    #pragma unroll
    for (int t = 0; t < TT; t++)
        o[t] = g_scr[(size_t)t * PLANE + v];

    float4* out = (float4*)(lat + (size_t)v * TT);
    out[0] = make_float4(o[0], o[1], o[2], o[3]);
    out[1] = make_float4(o[4], o[5], o[6], o[7]);
}

// ---------------------------------------------------------------------------
// fill work for one block (one bin per thread).
// ---------------------------------------------------------------------------
__device__ __forceinline__ void do_fill(int fb,
                                        float* __restrict__ buf,
                                        float* __restrict__ bmask)
{
    int b = fb * 256 + threadIdx.x;

    const float4* rec = &g_pts[(size_t)b * STORE_CAP];

    float w8[CAP];
    #pragma unroll
    for (int e = 0; e < CAP; e++) w8[e] = rec[e].w;

    int cnt = g_count[b];
    int m = min(cnt, STORE_CAP);

    int key[CAP];
    #pragma unroll
    for (int s = 0; s < CAP; s++) key[s] = 0x7FFFFFFF;

    #pragma unroll
    for (int e = 0; e < CAP; e++) {
        if (e >= m) break;
        int k = (__float_as_int(w8[e]) << 5) | e;
        #pragma unroll
        for (int j = 0; j < CAP; j++) {
            int lo = min(k, key[j]);
            int hi = max(k, key[j]);
            key[j] = lo;
            k = hi;
        }
    }
    for (int e = CAP; e < m; e++) {
        int k = (__float_as_int(rec[e].w) << 5) | e;
        #pragma unroll
        for (int j = 0; j < CAP; j++) {
            int lo = min(k, key[j]);
            int hi = max(k, key[j]);
            key[j] = lo;
            k = hi;
        }
    }

    int nval = min(cnt, CAP);
    float o[CAP * 3];
    float mk[CAP];
    #pragma unroll
    for (int s = 0; s < CAP; s++) {
        float x = 0.f, y = 0.f, z = 0.f, mv = 0.f;
        if (s < nval) {
            float4 r = rec[key[s] & (STORE_CAP - 1)];
            x = r.x; y = r.y; z = r.z; mv = 1.0f;
        }
        o[3*s + 0] = x; o[3*s + 1] = y; o[3*s + 2] = z;
        mk[s] = mv;
    }

    float4* bp = (float4*)(buf + (size_t)b * (CAP * 3));
    #pragma unroll
    for (int q = 0; q < 6; q++)
        bp[q] = make_float4(o[4*q + 0], o[4*q + 1], o[4*q + 2], o[4*q + 3]);

    float4* mp = (float4*)(bmask + (size_t)b * CAP);
    mp[0] = make_float4(mk[0], mk[1], mk[2], mk[3]);
    mp[1] = make_float4(mk[4], mk[5], mk[6], mk[7]);
}

// ---------------------------------------------------------------------------
// Kernel C: interleaved [transpose | fill]. Groups of 9: r<8 transpose, r==8 fill.
// ---------------------------------------------------------------------------
__global__ void __launch_bounds__(256)
transpose_fill_kernel(float* __restrict__ lat,
                      float* __restrict__ buf,
                      float* __restrict__ bmask)
{
    int g = blockIdx.x;
    int k = g / 9;
    int r = g - k * 9;
    if (r < 8) do_transpose(k * 8 + r, lat);
    else       do_fill(k, buf, bmask);
}

// ---------------------------------------------------------------------------
extern "C" void kernel_launch(void* const* d_in, const int* in_sizes, int n_in,
                              void* d_out, int out_size)
{
    const float* points = (const float*)d_in[0];
    const int*   mask   = (const int*)d_in[1];
    const int*   types  = (const int*)d_in[2];

    float* out   = (float*)d_out;
    float* lat   = out;                       // [128,128,128,8]
    float* buf   = out + LAT_ELEMS;           // [262144,8,3]
    float* bmask = buf + BUF_ELEMS;           // [262144,8]

    void* cptr = nullptr;
    cudaGetSymbolAddress(&cptr, g_count);
    cudaMemsetAsync(cptr, 0, (size_t)NUM_BINS * sizeof(int), 0);

    zero_bin_kernel<<<A_BLOCKS, 256>>>(points, mask, types);
    splat_kernel<<<SPLAT_BLOCKS, 256>>>();
    transpose_fill_kernel<<<C_BLOCKS, 256>>>(lat, buf, bmask);
}

// round 13
// speedup vs baseline: 1.0347x; 1.0347x over previous
#include <cuda_runtime.h>
#include <cuda_bf16.h>
#include <stdint.h>

#define N_POINTS  1048576
#define DD        64
#define NUM_BINS  (DD*DD*DD)         // 262144
#define LL        128
#define TT        8
#define CAP       8
#define STORE_CAP 32

#define LAT_ELEMS  (LL*LL*LL*TT)     // 16777216
#define BUF_ELEMS  (NUM_BINS*CAP*3)
#define PLANE      (LL*LL*LL)        // 2097152 floats per type-plane
#define XSLICE     (LL*LL)           // 16384

// grids
#define BIN_BLOCKS   (N_POINTS/256)               // 4096
#define SPLAT_BLOCKS (NUM_BINS*4/256)             // 4096 (4 slots/bin)
#define FILL_BLOCKS  (NUM_BINS/256)               // 1024
#define C_BLOCKS     (FILL_BLOCKS*9)              // 9216, groups of 9 (8 tr + 1 fill)

__device__ int    g_count[NUM_BINS];
__device__ __align__(16)  float4 g_pts[NUM_BINS * STORE_CAP]; // (x,y,z,(idx<<3)|t)
__device__ __align__(128) float  g_scr[TT * PLANE];           // [t][x][y][z]

// ---- vector reduction ------------------------------------------------------
__device__ __forceinline__ void red4(float* p, float a, float b, float c, float d) {
    asm volatile("red.global.add.v4.f32 [%0], {%1,%2,%3,%4};"
                 :: "l"(p), "f"(a), "f"(b), "f"(c), "f"(d) : "memory");
}

// ---- scalar bounds-checked splat (boundary + overflow path) ----------------
__device__ __forceinline__ void splat_scalar(float px, float py, float pz, int t)
{
    int cx = (int)floorf(px * 4.0f);
    int cy = (int)floorf(py * 4.0f);
    int cz = (int)floorf(pz * 4.0f);

    const float inv = 1.0f / (2.0f * 0.3f * 0.3f);
    float ex[3], ey[3], ez[3];
    #pragma unroll
    for (int o = 0; o < 3; o++) {
        float vx = px - ((float)(cx + o - 1) + 0.5f) * 0.25f;
        float vy = py - ((float)(cy + o - 1) + 0.5f) * 0.25f;
        float vz = pz - ((float)(cz + o - 1) + 0.5f) * 0.25f;
        ex[o] = __expf(-vx * vx * inv);
        ey[o] = __expf(-vy * vy * inv);
        ez[o] = __expf(-vz * vz * inv);
    }
    float* pl = g_scr + (size_t)t * PLANE;
    #pragma unroll
    for (int ix = 0; ix < 3; ix++) {
        int x = cx + ix - 1;
        if ((unsigned)x >= (unsigned)LL) continue;
        #pragma unroll
        for (int iy = 0; iy < 3; iy++) {
            int y = cy + iy - 1;
            if ((unsigned)y >= (unsigned)LL) continue;
            float exy = ex[ix] * ey[iy];
            #pragma unroll
            for (int iz = 0; iz < 3; iz++) {
                int z = cz + iz - 1;
                if ((unsigned)z >= (unsigned)LL) continue;
                atomicAdd(pl + x * XSLICE + y * LL + z, exy * ez[iz]);
            }
        }
    }
}

// ---------------------------------------------------------------------------
// Kernel A: bin scatter only (scalar, high-occupancy version).
// ---------------------------------------------------------------------------
__global__ void __launch_bounds__(256)
bin_kernel(const float* __restrict__ pts,
           const int* __restrict__ mask,
           const int* __restrict__ types)
{
    int i = blockIdx.x * blockDim.x + threadIdx.x;
    if (i >= N_POINTS) return;
    if (!mask[i]) return;

    float px = pts[3*i + 0];
    float py = pts[3*i + 1];
    float pz = pts[3*i + 2];
    int   t  = types[i];

    int bx = min(max((int)floorf(px * 2.0f), 0), DD - 1);
    int by = min(max((int)floorf(py * 2.0f), 0), DD - 1);
    int bz = min(max((int)floorf(pz * 2.0f), 0), DD - 1);
    int bin = (bx * DD + by) * DD + bz;
    int pos = atomicAdd(&g_count[bin], 1);
    if (pos < STORE_CAP) {
        g_pts[bin * STORE_CAP + pos] =
            make_float4(px, py, pz, __int_as_float((i << 3) | t));
    } else {
        splat_scalar(px, py, pz, t);   // P ~ 1e-22, keeps result exact
    }
}

// ---------------------------------------------------------------------------
// Kernel B: splat only (bin = tid/4, slot = tid%4) — shifted-u8 two-red4.
// Runs immediately after the scratch memset so the zeroed lines are L2-hot.
// ---------------------------------------------------------------------------
__global__ void __launch_bounds__(256)
splat_kernel()
{
    int tid = blockIdx.x * 256 + threadIdx.x;
    int bin  = tid >> 2;
    int slot = tid & 3;

    int m = min(g_count[bin], STORE_CAP);
    for (int s = slot; s < m; s += 4) {
        float4 r = g_pts[bin * STORE_CAP + s];
        float px = r.x, py = r.y, pz = r.z;
        int t = __float_as_int(r.w) & 7;

        int cx = (int)floorf(px * 4.0f);
        int cy = (int)floorf(py * 4.0f);
        int cz = (int)floorf(pz * 4.0f);

        bool interior = ((unsigned)(cx - 1) < (unsigned)(LL - 2)) &&
                        ((unsigned)(cy - 1) < (unsigned)(LL - 2)) &&
                        ((unsigned)(cz - 1) < (unsigned)(LL - 2));
        if (!interior) { splat_scalar(px, py, pz, t); continue; }

        const float inv = 1.0f / (2.0f * 0.3f * 0.3f);
        float ex[3], ey[3], ez[3];
        #pragma unroll
        for (int o = 0; o < 3; o++) {
            float vx = px - ((float)(cx + o - 1) + 0.5f) * 0.25f;
            float vy = py - ((float)(cy + o - 1) + 0.5f) * 0.25f;
            float vz = pz - ((float)(cz + o - 1) + 0.5f) * 0.25f;
            ex[o] = __expf(-vx * vx * inv);
            ey[o] = __expf(-vy * vy * inv);
            ez[o] = __expf(-vz * vz * inv);
        }

        int zb = cz - 1;
        int a  = zb & 3;

        float u[8];
        #pragma unroll
        for (int q = 0; q < 8; q++) {
            int d = q - a;
            u[q] = (d == 0) ? ez[0] : (d == 1) ? ez[1] : (d == 2) ? ez[2] : 0.0f;
        }
        bool two = (a >= 2);

        float* q0 = g_scr + (size_t)t * PLANE
                  + (cx - 1) * XSLICE + (cy - 1) * LL + (zb - a);

        #pragma unroll
        for (int ix = 0; ix < 3; ix++) {
            #pragma unroll
            for (int iy = 0; iy < 3; iy++) {
                float w = ex[ix] * ey[iy];
                float* p = q0 + ix * XSLICE + iy * LL;
                red4(p, w*u[0], w*u[1], w*u[2], w*u[3]);
                if (two)
                    red4(p + 4, w*u[4], w*u[5], w*u[6], w*u[7]);
            }
        }
    }
}

// ---------------------------------------------------------------------------
// transpose work for one block: [t][x][y][z] -> [x][y][z][t]
// ---------------------------------------------------------------------------
__device__ __forceinline__ void do_transpose(int tb, float* __restrict__ lat)
{
    int v = tb * 256 + threadIdx.x;   // (x*128+y)*128+z

    float o[TT];
    #pragma unroll
    for (int t = 0; t < TT; t++)
        o[t] = g_scr[(size_t)t * PLANE + v];

    float4* out = (float4*)(lat + (size_t)v * TT);
    out[0] = make_float4(o[0], o[1], o[2], o[3]);
    out[1] = make_float4(o[4], o[5], o[6], o[7]);
}

// ---------------------------------------------------------------------------
// fill work for one block (one bin per thread).
// ---------------------------------------------------------------------------
__device__ __forceinline__ void do_fill(int fb,
                                        float* __restrict__ buf,
                                        float* __restrict__ bmask)
{
    int b = fb * 256 + threadIdx.x;

    const float4* rec = &g_pts[(size_t)b * STORE_CAP];

    float w8[CAP];
    #pragma unroll
    for (int e = 0; e < CAP; e++) w8[e] = rec[e].w;

    int cnt = g_count[b];
    int m = min(cnt, STORE_CAP);

    int key[CAP];
    #pragma unroll
    for (int s = 0; s < CAP; s++) key[s] = 0x7FFFFFFF;

    #pragma unroll
    for (int e = 0; e < CAP; e++) {
        if (e >= m) break;
        int k = (__float_as_int(w8[e]) << 5) | e;
        #pragma unroll
        for (int j = 0; j < CAP; j++) {
            int lo = min(k, key[j]);
            int hi = max(k, key[j]);
            key[j] = lo;
            k = hi;
        }
    }
    for (int e = CAP; e < m; e++) {
        int k = (__float_as_int(rec[e].w) << 5) | e;
        #pragma unroll
        for (int j = 0; j < CAP; j++) {
            int lo = min(k, key[j]);
            int hi = max(k, key[j]);
            key[j] = lo;
            k = hi;
        }
    }

    int nval = min(cnt, CAP);
    float o[CAP * 3];
    float mk[CAP];
    #pragma unroll
    for (int s = 0; s < CAP; s++) {
        float x = 0.f, y = 0.f, z = 0.f, mv = 0.f;
        if (s < nval) {
            float4 r = rec[key[s] & (STORE_CAP - 1)];
            x = r.x; y = r.y; z = r.z; mv = 1.0f;
        }
        o[3*s + 0] = x; o[3*s + 1] = y; o[3*s + 2] = z;
        mk[s] = mv;
    }

    float4* bp = (float4*)(buf + (size_t)b * (CAP * 3));
    #pragma unroll
    for (int q = 0; q < 6; q++)
        bp[q] = make_float4(o[4*q + 0], o[4*q + 1], o[4*q + 2], o[4*q + 3]);

    float4* mp = (float4*)(bmask + (size_t)b * CAP);
    mp[0] = make_float4(mk[0], mk[1], mk[2], mk[3]);
    mp[1] = make_float4(mk[4], mk[5], mk[6], mk[7]);
}

// ---------------------------------------------------------------------------
// Kernel C: interleaved [transpose | fill]. Groups of 9: r<8 transpose, r==8 fill.
// ---------------------------------------------------------------------------
__global__ void __launch_bounds__(256)
transpose_fill_kernel(float* __restrict__ lat,
                      float* __restrict__ buf,
                      float* __restrict__ bmask)
{
    int g = blockIdx.x;
    int k = g / 9;
    int r = g - k * 9;
    if (r < 8) do_transpose(k * 8 + r, lat);
    else       do_fill(k, buf, bmask);
}

// ---------------------------------------------------------------------------
extern "C" void kernel_launch(void* const* d_in, const int* in_sizes, int n_in,
                              void* d_out, int out_size)
{
    const float* points = (const float*)d_in[0];
    const int*   mask   = (const int*)d_in[1];
    const int*   types  = (const int*)d_in[2];

    float* out   = (float*)d_out;
    float* lat   = out;                       // [128,128,128,8]
    float* buf   = out + LAT_ELEMS;           // [262144,8,3]
    float* bmask = buf + BUF_ELEMS;           // [262144,8]

    void* cptr = nullptr;
    cudaGetSymbolAddress(&cptr, g_count);
    cudaMemsetAsync(cptr, 0, (size_t)NUM_BINS * sizeof(int), 0);

    // 1) bin, 2) zero scratch LAST-MINUTE (L2-hot for the splat), 3) splat,
    // 4) transpose || fill
    bin_kernel<<<BIN_BLOCKS, 256>>>(points, mask, types);

    void* sptr = nullptr;
    cudaGetSymbolAddress(&sptr, g_scr);
    cudaMemsetAsync(sptr, 0, (size_t)TT * PLANE * sizeof(float), 0);

    splat_kernel<<<SPLAT_BLOCKS, 256>>>();
    transpose_fill_kernel<<<C_BLOCKS, 256>>>(lat, buf, bmask);
}

// round 14
// speedup vs baseline: 1.0474x; 1.0123x over previous
#include <cuda_runtime.h>
#include <cuda_bf16.h>
#include <stdint.h>

#define N_POINTS  1048576
#define DD        64
#define NUM_BINS  (DD*DD*DD)         // 262144
#define LL        128
#define TT        8
#define CAP       8
#define STORE_CAP 32
#define OVF_CAP   4096

#define LAT_ELEMS  (LL*LL*LL*TT)     // 16777216
#define BUF_ELEMS  (NUM_BINS*CAP*3)
#define PLANE      (LL*LL*LL)        // 2097152 floats per type-plane
#define XSLICE     (LL*LL)           // 16384

// grids
#define BIN_BLOCKS   (N_POINTS/256)               // 4096
#define ZERO_BLOCKS  ((TT*PLANE/4)/256)           // 16384 (1 float4/thread)
#define A_BLOCKS     (BIN_BLOCKS + ZERO_BLOCKS)   // 20480: [bin | zero-last]
#define SPLAT_BLOCKS (NUM_BINS*4/256)             // 4096 (4 slots/bin)
#define FILL_BLOCKS  (NUM_BINS/256)               // 1024
#define C_BLOCKS     (FILL_BLOCKS*9)              // 9216, groups of 9 (8 tr + 1 fill)

__device__ int    g_count[NUM_BINS];
__device__ int    g_ovf_count;
__device__ __align__(16)  float4 g_ovf[OVF_CAP];
__device__ __align__(16)  float4 g_pts[NUM_BINS * STORE_CAP]; // (x,y,z,(idx<<3)|t)
__device__ __align__(128) float  g_scr[TT * PLANE];           // [t][x][y][z]

// ---- vector reductions ------------------------------------------------------
__device__ __forceinline__ void red4(float* p, float a, float b, float c, float d) {
    asm volatile("red.global.add.v4.f32 [%0], {%1,%2,%3,%4};"
                 :: "l"(p), "f"(a), "f"(b), "f"(c), "f"(d) : "memory");
}
__device__ __forceinline__ void red2(float* p, float a, float b) {
    asm volatile("red.global.add.v2.f32 [%0], {%1,%2};"
                 :: "l"(p), "f"(a), "f"(b) : "memory");
}

// ---- scalar bounds-checked splat (boundary + overflow path) ----------------
__device__ __forceinline__ void splat_scalar(float px, float py, float pz, int t)
{
    int cx = (int)floorf(px * 4.0f);
    int cy = (int)floorf(py * 4.0f);
    int cz = (int)floorf(pz * 4.0f);

    const float inv = 1.0f / (2.0f * 0.3f * 0.3f);
    float ex[3], ey[3], ez[3];
    #pragma unroll
    for (int o = 0; o < 3; o++) {
        float vx = px - ((float)(cx + o - 1) + 0.5f) * 0.25f;
        float vy = py - ((float)(cy + o - 1) + 0.5f) * 0.25f;
        float vz = pz - ((float)(cz + o - 1) + 0.5f) * 0.25f;
        ex[o] = __expf(-vx * vx * inv);
        ey[o] = __expf(-vy * vy * inv);
        ez[o] = __expf(-vz * vz * inv);
    }
    #pragma unroll
    for (int ix = 0; ix < 3; ix++) {
        int x = cx + ix - 1;
        if ((unsigned)x >= (unsigned)LL) continue;
        #pragma unroll
        for (int iy = 0; iy < 3; iy++) {
            int y = cy + iy - 1;
            if ((unsigned)y >= (unsigned)LL) continue;
            float exy = ex[ix] * ey[iy];
            #pragma unroll
            for (int iz = 0; iz < 3; iz++) {
                int z = cz + iz - 1;
                if ((unsigned)z >= (unsigned)LL) continue;
                atomicAdd(g_scr + (size_t)t * PLANE + x * XSLICE + y * LL + z,
                          exy * ez[iz]);
            }
        }
    }
}

// ---------------------------------------------------------------------------
// Kernel A: [bin blocks first | zero blocks last]. Zero blocks run at the
// tail of the kernel, leaving the scratch zeros L2-hot for the splat while
// overlapping with bin's latency-bound execution.
// ---------------------------------------------------------------------------
__global__ void __launch_bounds__(256)
bin_zero_kernel(const float* __restrict__ pts,
                const int* __restrict__ mask,
                const int* __restrict__ types)
{
    int g = blockIdx.x;

    if (g >= BIN_BLOCKS) {
        int zid = (g - BIN_BLOCKS) * 256 + threadIdx.x;
        ((float4*)g_scr)[zid] = make_float4(0.f, 0.f, 0.f, 0.f);
        return;
    }

    int i = g * 256 + threadIdx.x;
    if (!mask[i]) return;

    float px = pts[3*i + 0];
    float py = pts[3*i + 1];
    float pz = pts[3*i + 2];
    int   t  = types[i];

    int bx = min(max((int)floorf(px * 2.0f), 0), DD - 1);
    int by = min(max((int)floorf(py * 2.0f), 0), DD - 1);
    int bz = min(max((int)floorf(pz * 2.0f), 0), DD - 1);
    int bin = (bx * DD + by) * DD + bz;
    int pos = atomicAdd(&g_count[bin], 1);
    if (pos < STORE_CAP) {
        g_pts[bin * STORE_CAP + pos] =
            make_float4(px, py, pz, __int_as_float((i << 3) | t));
    } else {
        // P ~ 1e-22: park in overflow list; splat_kernel handles it after
        // zeroing is complete (no race with the zero blocks).
        int op = atomicAdd(&g_ovf_count, 1);
        if (op < OVF_CAP)
            g_ovf[op] = make_float4(px, py, pz, __int_as_float((i << 3) | t));
    }
}

// ---------------------------------------------------------------------------
// Kernel B: splat (bin = tid/4, slot = tid%4) — shifted-u8 red4+red2.
// Since a<=3, the spill into the next quad covers at most u[4],u[5].
// ---------------------------------------------------------------------------
__global__ void __launch_bounds__(256)
splat_kernel()
{
    int tid = blockIdx.x * 256 + threadIdx.x;
    int bin  = tid >> 2;
    int slot = tid & 3;

    // overflow drain (normally zero entries)
    if (blockIdx.x == 0) {
        int n = min(g_ovf_count, OVF_CAP);
        for (int e = threadIdx.x; e < n; e += 256) {
            float4 r = g_ovf[e];
            splat_scalar(r.x, r.y, r.z, __float_as_int(r.w) & 7);
        }
    }

    int m = min(g_count[bin], STORE_CAP);
    for (int s = slot; s < m; s += 4) {
        float4 r = g_pts[bin * STORE_CAP + s];
        float px = r.x, py = r.y, pz = r.z;
        int t = __float_as_int(r.w) & 7;

        int cx = (int)floorf(px * 4.0f);
        int cy = (int)floorf(py * 4.0f);
        int cz = (int)floorf(pz * 4.0f);

        bool interior = ((unsigned)(cx - 1) < (unsigned)(LL - 2)) &&
                        ((unsigned)(cy - 1) < (unsigned)(LL - 2)) &&
                        ((unsigned)(cz - 1) < (unsigned)(LL - 2));
        if (!interior) { splat_scalar(px, py, pz, t); continue; }

        const float inv = 1.0f / (2.0f * 0.3f * 0.3f);
        float ex[3], ey[3], ez[3];
        #pragma unroll
        for (int o = 0; o < 3; o++) {
            float vx = px - ((float)(cx + o - 1) + 0.5f) * 0.25f;
            float vy = py - ((float)(cy + o - 1) + 0.5f) * 0.25f;
            float vz = pz - ((float)(cz + o - 1) + 0.5f) * 0.25f;
            ex[o] = __expf(-vx * vx * inv);
            ey[o] = __expf(-vy * vy * inv);
            ez[o] = __expf(-vz * vz * inv);
        }

        int zb = cz - 1;
        int a  = zb & 3;

        // shifted ez pattern over 6 cells: u[a..a+2] = ez[0..2]
        float u[6];
        #pragma unroll
        for (int q = 0; q < 6; q++) {
            int d = q - a;
            u[q] = (d == 0) ? ez[0] : (d == 1) ? ez[1] : (d == 2) ? ez[2] : 0.0f;
        }
        bool two = (a >= 2);

        float* q0 = g_scr + (size_t)t * PLANE
                  + (cx - 1) * XSLICE + (cy - 1) * LL + (zb - a);

        #pragma unroll
        for (int ix = 0; ix < 3; ix++) {
            #pragma unroll
            for (int iy = 0; iy < 3; iy++) {
                float w = ex[ix] * ey[iy];
                float* p = q0 + ix * XSLICE + iy * LL;
                red4(p, w*u[0], w*u[1], w*u[2], w*u[3]);
                if (two)
                    red2(p + 4, w*u[4], w*u[5]);
            }
        }
    }
}

// ---------------------------------------------------------------------------
// transpose work for one block: [t][x][y][z] -> [x][y][z][t]
// ---------------------------------------------------------------------------
__device__ __forceinline__ void do_transpose(int tb, float* __restrict__ lat)
{
    int v = tb * 256 + threadIdx.x;   // (x*128+y)*128+z

    float o[TT];
    #pragma unroll
    for (int t = 0; t < TT; t++)
        o[t] = g_scr[(size_t)t * PLANE + v];

    float4* out = (float4*)(lat + (size_t)v * TT);
    out[0] = make_float4(o[0], o[1], o[2], o[3]);
    out[1] = make_float4(o[4], o[5], o[6], o[7]);
}

// ---------------------------------------------------------------------------
// fill work for one block (one bin per thread).
// ---------------------------------------------------------------------------
__device__ __forceinline__ void do_fill(int fb,
                                        float* __restrict__ buf,
                                        float* __restrict__ bmask)
{
    int b = fb * 256 + threadIdx.x;

    const float4* rec = &g_pts[(size_t)b * STORE_CAP];

    float w8[CAP];
    #pragma unroll
    for (int e = 0; e < CAP; e++) w8[e] = rec[e].w;

    int cnt = g_count[b];
    int m = min(cnt, STORE_CAP);

    int key[CAP];
    #pragma unroll
    for (int s = 0; s < CAP; s++) key[s] = 0x7FFFFFFF;

    #pragma unroll
    for (int e = 0; e < CAP; e++) {
        if (e >= m) break;
        int k = (__float_as_int(w8[e]) << 5) | e;
        #pragma unroll
        for (int j = 0; j < CAP; j++) {
            int lo = min(k, key[j]);
            int hi = max(k, key[j]);
            key[j] = lo;
            k = hi;
        }
    }
    for (int e = CAP; e < m; e++) {
        int k = (__float_as_int(rec[e].w) << 5) | e;
        #pragma unroll
        for (int j = 0; j < CAP; j++) {
            int lo = min(k, key[j]);
            int hi = max(k, key[j]);
            key[j] = lo;
            k = hi;
        }
    }

    int nval = min(cnt, CAP);
    float o[CAP * 3];
    float mk[CAP];
    #pragma unroll
    for (int s = 0; s < CAP; s++) {
        float x = 0.f, y = 0.f, z = 0.f, mv = 0.f;
        if (s < nval) {
            float4 r = rec[key[s] & (STORE_CAP - 1)];
            x = r.x; y = r.y; z = r.z; mv = 1.0f;
        }
        o[3*s + 0] = x; o[3*s + 1] = y; o[3*s + 2] = z;
        mk[s] = mv;
    }

    float4* bp = (float4*)(buf + (size_t)b * (CAP * 3));
    #pragma unroll
    for (int q = 0; q < 6; q++)
        bp[q] = make_float4(o[4*q + 0], o[4*q + 1], o[4*q + 2], o[4*q + 3]);

    float4* mp = (float4*)(bmask + (size_t)b * CAP);
    mp[0] = make_float4(mk[0], mk[1], mk[2], mk[3]);
    mp[1] = make_float4(mk[4], mk[5], mk[6], mk[7]);
}

// ---------------------------------------------------------------------------
// Kernel C: interleaved [transpose | fill]. Groups of 9: r<8 transpose, r==8 fill.
// ---------------------------------------------------------------------------
__global__ void __launch_bounds__(256)
transpose_fill_kernel(float* __restrict__ lat,
                      float* __restrict__ buf,
                      float* __restrict__ bmask)
{
    int g = blockIdx.x;
    int k = g / 9;
    int r = g - k * 9;
    if (r < 8) do_transpose(k * 8 + r, lat);
    else       do_fill(k, buf, bmask);
}

// ---------------------------------------------------------------------------
extern "C" void kernel_launch(void* const* d_in, const int* in_sizes, int n_in,
                              void* d_out, int out_size)
{
    const float* points = (const float*)d_in[0];
    const int*   mask   = (const int*)d_in[1];
    const int*   types  = (const int*)d_in[2];

    float* out   = (float*)d_out;
    float* lat   = out;                       // [128,128,128,8]
    float* buf   = out + LAT_ELEMS;           // [262144,8,3]
    float* bmask = buf + BUF_ELEMS;           // [262144,8]

    void* cptr = nullptr;
    cudaGetSymbolAddress(&cptr, g_count);
    cudaMemsetAsync(cptr, 0, (size_t)NUM_BINS * sizeof(int), 0);
    void* optr = nullptr;
    cudaGetSymbolAddress(&optr, g_ovf_count);
    cudaMemsetAsync(optr, 0, sizeof(int), 0);

    bin_zero_kernel<<<A_BLOCKS, 256>>>(points, mask, types);
    splat_kernel<<<SPLAT_BLOCKS, 256>>>();
    transpose_fill_kernel<<<C_BLOCKS, 256>>>(lat, buf, bmask);
}